// round 13
// baseline (speedup 1.0000x reference)
#include <cuda_runtime.h>
#include <stdint.h>

#define NMAX 50000
#define DD 128
#define NPW 8
#define HTPB 1024
#define HGRID 148
#define GSIZE (HGRID * HTPB)
#define NWARPS (GSIZE / 32)

// Scratch (no device allocs allowed)
__device__ float g_deg[NMAX];
__device__ float g_y[NMAX];
__device__ float g_p[NMAX];
__device__ float g_q[NMAX];
__device__ float g_r[NMAX];
__device__ float g_acc1[NMAX];
__device__ float g_acc2[NMAX];

// grid barrier state (self-resetting across calls)
__device__ int g_count;
__device__ int g_sense;

__device__ __forceinline__ void grid_bar(int* s_sense) {
    __syncthreads();
    if (threadIdx.x == 0) {
        __threadfence();
        int next = *s_sense ^ 1;
        if (atomicAdd(&g_count, 1) == HGRID - 1) {
            g_count = 0;
            __threadfence();
            atomicExch(&g_sense, next);
        } else {
            while (atomicAdd(&g_sense, 0) != next) { }
        }
        *s_sense = next;
    }
    __syncthreads();
}

__global__ void __launch_bounds__(HTPB, 1)
k_fused(const float* __restrict__ x, const long long* __restrict__ edge,
        const float* __restrict__ W, const float* __restrict__ b,
        float* __restrict__ out, int e_cnt, int n) {
    __shared__ int s_sense;
    __shared__ int s_mode;
    const int tid  = threadIdx.x;
    const int gtid = blockIdx.x * HTPB + tid;
    const int* e32 = (const int*)edge;

    // entry: read barrier sense; detect index dtype (per block, deterministic)
    if (tid == 0) s_sense = atomicAdd(&g_sense, 0);
    if (tid < 32) {
        long long v = edge[tid];
        unsigned ok = __ballot_sync(0xffffffffu, v >= 0 && v < (long long)n);
        if (tid == 0) s_mode = (ok == 0xffffffffu) ? 1 : 0;
    }
    __syncthreads();
    const int mode = s_mode;

    // ---- Phase A: init ----
    for (int i = gtid; i < n; i += GSIZE) {
        g_deg[i]  = 1.0f;
        g_acc1[i] = 0.0f;
        g_acc2[i] = 0.0f;
    }
    grid_bar(&s_sense);

    // ---- Phase B: y = x.W (warp per NPW nodes) + deg atomics ----
    {
        int warp = gtid >> 5;
        int lane = tid & 31;
        int ngroups = (n + NPW - 1) / NPW;
        float4 w = __ldg(&((const float4*)W)[lane]);
        for (int g = warp; g < ngroups; g += NWARPS) {
            int base = g * NPW;
            float s[NPW];
            #pragma unroll
            for (int k = 0; k < NPW; k++) {
                int node = base + k;
                float4 a = (node < n) ? ((const float4*)(x + (size_t)node * DD))[lane]
                                      : make_float4(0.f, 0.f, 0.f, 0.f);
                s[k] = a.x * w.x + a.y * w.y + a.z * w.z + a.w * w.w;
            }
            #pragma unroll
            for (int off = 16; off > 0; off >>= 1) {
                #pragma unroll
                for (int k = 0; k < NPW; k++)
                    s[k] += __shfl_down_sync(0xffffffffu, s[k], off);
            }
            if (lane == 0) {
                #pragma unroll
                for (int k = 0; k < NPW; k++)
                    if (base + k < n) g_y[base + k] = s[k];
            }
        }
        for (int e = gtid; e < e_cnt; e += GSIZE) {
            int dst = mode ? (int)edge[e_cnt + e] : e32[e_cnt + e];
            if ((unsigned)dst < (unsigned)n)
                atomicAdd(&g_deg[dst], 1.0f);
        }
    }
    grid_bar(&s_sense);

    // ---- Phase C: p = rsqrt(deg), q = p*y ----
    for (int i = gtid; i < n; i += GSIZE) {
        float p = rsqrtf(__ldcg(&g_deg[i]));
        g_p[i] = p;
        g_q[i] = p * __ldcg(&g_y[i]);
    }
    grid_bar(&s_sense);

    // ---- Phase D: hop1  acc1[dst] += q[src] ----
    for (int e = gtid; e < e_cnt; e += GSIZE) {
        int src = mode ? (int)edge[e] : e32[e];
        int dst = mode ? (int)edge[e_cnt + e] : e32[e_cnt + e];
        if ((unsigned)src < (unsigned)n && (unsigned)dst < (unsigned)n)
            atomicAdd(&g_acc1[dst], __ldcg(&g_q[src]));
    }
    grid_bar(&s_sense);

    // ---- Phase E: r = p*p*(q + acc1) ----
    for (int i = gtid; i < n; i += GSIZE) {
        float p = __ldcg(&g_p[i]);
        g_r[i] = p * p * (__ldcg(&g_q[i]) + __ldcg(&g_acc1[i]));
    }
    grid_bar(&s_sense);

    // ---- Phase F: hop2  acc2[dst] += r[src] ----
    for (int e = gtid; e < e_cnt; e += GSIZE) {
        int src = mode ? (int)edge[e] : e32[e];
        int dst = mode ? (int)edge[e_cnt + e] : e32[e_cnt + e];
        if ((unsigned)src < (unsigned)n && (unsigned)dst < (unsigned)n)
            atomicAdd(&g_acc2[dst], __ldcg(&g_r[src]));
    }
    grid_bar(&s_sense);

    // ---- Phase G: out = p*(r + acc2) + b ----
    float bias = __ldg(&b[0]);
    for (int i = gtid; i < n; i += GSIZE) {
        out[i] = __ldcg(&g_p[i]) * (__ldcg(&g_r[i]) + __ldcg(&g_acc2[i])) + bias;
    }
}

extern "C" void kernel_launch(void* const* d_in, const int* in_sizes, int n_in,
                              void* d_out, int out_size) {
    const float*     x    = (const float*)d_in[0];       // [N, 128]
    const long long* edge = (const long long*)d_in[1];   // [2, E] indices
    const float*     W    = (const float*)d_in[2];       // [1, 128]
    const float*     b    = (const float*)d_in[3];       // [1]
    float*           out  = (float*)d_out;               // [N]

    int n = in_sizes[0] / DD;
    if (n > NMAX) n = NMAX;
    const int e_cnt = in_sizes[1] / 2;

    k_fused<<<HGRID, HTPB>>>(x, edge, W, b, out, e_cnt, n);
}

// round 14
// speedup vs baseline: 1.2494x; 1.2494x over previous
#include <cuda_runtime.h>
#include <stdint.h>

#define NMAX 50000
#define DD 128
#define NPW 8      // nodes per warp in proj-dot
#define TPB 256

// Scratch — zero-initialized at module load; every kernel_launch call leaves
// deg/acc1/acc2 zeroed again (k_final resets), so no init kernel is needed.
__device__ float g_deg[NMAX];
__device__ float g_y[NMAX];     // x . W
__device__ float g_p[NMAX];
__device__ float g_q[NMAX];     // p * y   (hop-1 message value)
__device__ float g_r[NMAX];     // p * t   (hop-2 message value)
__device__ float g_acc1[NMAX];  // sum of q[src] per dst
__device__ float g_acc2[NMAX];  // sum of r[src] per dst
__device__ int   g_mode;        // 1 = indices are int64, 0 = int32

// ---------------------------------------------------------------------------
// K1 (fused, block-specialized):
//   block 0, warp 0 additionally: detect index dtype
//   blocks [0, edgeBlocks)   : deg[dst] += 1, one edge per thread (deg from 0)
//   blocks [edgeBlocks, ...) : y[node] = x[node] . W   (warp handles NPW nodes)
__global__ void k_deg_dot(const float* __restrict__ x, const float* __restrict__ W,
                          const long long* __restrict__ edge,
                          int e_cnt, int n, int edgeBlocks) {
    if (blockIdx.x == 0 && threadIdx.x < 32) {
        long long v = edge[threadIdx.x];
        unsigned ok = __ballot_sync(0xffffffffu, v >= 0 && v < (long long)n);
        if (threadIdx.x == 0) g_mode = (ok == 0xffffffffu) ? 1 : 0;
    }
    if (blockIdx.x < edgeBlocks) {
        int e = blockIdx.x * blockDim.x + threadIdx.x;
        if (e < e_cnt) {
            // dtype known without g_mode round-trip: re-derive locally from the
            // same probe rule is racy across blocks, so read indices both ways
            // is not possible — instead detect per-block (cheap, deterministic).
            __shared__ int s_mode;
            if (threadIdx.x < 32) {
                long long v = edge[threadIdx.x];
                unsigned ok = __ballot_sync(0xffffffffu, v >= 0 && v < (long long)n);
                if (threadIdx.x == 0) s_mode = (ok == 0xffffffffu) ? 1 : 0;
            }
            __syncthreads();
            int dst = s_mode ? (int)edge[e_cnt + e] : ((const int*)edge)[e_cnt + e];
            if ((unsigned)dst < (unsigned)n)
                atomicAdd(&g_deg[dst], 1.0f);
        }
    } else {
        int bid = blockIdx.x - edgeBlocks;
        int warp = (bid * blockDim.x + threadIdx.x) >> 5;
        int lane = threadIdx.x & 31;
        int base = warp * NPW;
        if (base >= n) return;

        float4 w = __ldg(&((const float4*)W)[lane]);

        float4 a[NPW];
        #pragma unroll
        for (int k = 0; k < NPW; k++) {
            int node = base + k;
            if (node < n)
                a[k] = ((const float4*)(x + (size_t)node * DD))[lane];
            else
                a[k] = make_float4(0.f, 0.f, 0.f, 0.f);
        }

        float s[NPW];
        #pragma unroll
        for (int k = 0; k < NPW; k++)
            s[k] = a[k].x * w.x + a[k].y * w.y + a[k].z * w.z + a[k].w * w.w;

        #pragma unroll
        for (int off = 16; off > 0; off >>= 1) {
            #pragma unroll
            for (int k = 0; k < NPW; k++)
                s[k] += __shfl_down_sync(0xffffffffu, s[k], off);
        }

        if (lane == 0) {
            #pragma unroll
            for (int k = 0; k < NPW; k++) {
                int node = base + k;
                if (node < n) g_y[node] = s[k];
            }
        }
    }
}

// ---------------------------------------------------------------------------
// K2: p = rsqrt(deg + 1)  (self-loop folded in), q = p*y
__global__ void k_pq(int n) {
    int i = blockIdx.x * blockDim.x + threadIdx.x;
    if (i < n) {
        float p = rsqrtf(g_deg[i] + 1.0f);
        g_p[i] = p;
        g_q[i] = p * g_y[i];
    }
}

// ---------------------------------------------------------------------------
// Edge sweep: acc[dst] += val[src].  ONE edge per thread (measured optimum).
__device__ __forceinline__ void edge_sweep(const long long* __restrict__ edge,
                                           int e_cnt, int n,
                                           const float* __restrict__ val,
                                           float* __restrict__ acc) {
    int e = blockIdx.x * blockDim.x + threadIdx.x;
    if (e < e_cnt) {
        int src, dst;
        if (g_mode) {
            src = (int)edge[e];
            dst = (int)edge[e_cnt + e];
        } else {
            const int* e32 = (const int*)edge;
            src = e32[e];
            dst = e32[e_cnt + e];
        }
        if ((unsigned)src < (unsigned)n && (unsigned)dst < (unsigned)n)
            atomicAdd(&acc[dst], val[src]);
    }
}

__global__ void k_hop1(const long long* __restrict__ edge, int e_cnt, int n) {
    edge_sweep(edge, e_cnt, n, g_q, g_acc1);
}

__global__ void k_hop2(const long long* __restrict__ edge, int e_cnt, int n) {
    edge_sweep(edge, e_cnt, n, g_r, g_acc2);
}

// ---------------------------------------------------------------------------
// K4: r = p*p*(q + acc1)
__global__ void k_mid(int n) {
    int i = blockIdx.x * blockDim.x + threadIdx.x;
    if (i < n) {
        float p = g_p[i];
        g_r[i] = p * p * (g_q[i] + g_acc1[i]);
    }
}

// K6: out[i] = p*(r + acc2) + b ; reset scratch to zero for the next call
__global__ void k_final(float* __restrict__ out, const float* __restrict__ b, int n) {
    int i = blockIdx.x * blockDim.x + threadIdx.x;
    if (i < n) {
        out[i] = g_p[i] * (g_r[i] + g_acc2[i]) + b[0];
        g_deg[i]  = 0.0f;
        g_acc1[i] = 0.0f;
        g_acc2[i] = 0.0f;
    }
}

extern "C" void kernel_launch(void* const* d_in, const int* in_sizes, int n_in,
                              void* d_out, int out_size) {
    const float*     x    = (const float*)d_in[0];       // [N, 128]
    const long long* edge = (const long long*)d_in[1];   // [2, E] indices
    const float*     W    = (const float*)d_in[2];       // [1, 128]
    const float*     b    = (const float*)d_in[3];       // [1]
    float*           out  = (float*)d_out;               // [N]

    int n = in_sizes[0] / DD;
    if (n > NMAX) n = NMAX;
    const int e_cnt = in_sizes[1] / 2;

    const int nBlkN = (n + TPB - 1) / TPB;
    const int nBlkE = (e_cnt + TPB - 1) / TPB;            // one edge / thread
    const int nWarps = (n + NPW - 1) / NPW;
    const int nBlkW = (nWarps * 32 + TPB - 1) / TPB;

    k_deg_dot<<<nBlkE + nBlkW, TPB>>>(x, W, edge, e_cnt, n, nBlkE);
    k_pq<<<nBlkN, TPB>>>(n);
    k_hop1<<<nBlkE, TPB>>>(edge, e_cnt, n);
    k_mid<<<nBlkN, TPB>>>(n);
    k_hop2<<<nBlkE, TPB>>>(edge, e_cnt, n);
    k_final<<<nBlkN, TPB>>>(out, b, n);
}

// round 15
// speedup vs baseline: 1.3222x; 1.0583x over previous
#include <cuda_runtime.h>
#include <stdint.h>

#define NMAX 50000
#define DD 128
#define NPW 8      // nodes per warp in proj-dot
#define TPB 256

// Scratch — zero-initialized at module load; every kernel_launch call leaves
// deg/acc1/acc2 zeroed again (k_final resets), so no init kernel is needed.
__device__ float g_deg[NMAX];
__device__ float g_y[NMAX];     // x . W
__device__ float g_p[NMAX];
__device__ float g_q[NMAX];     // p * y   (hop-1 message value)
__device__ float g_r[NMAX];     // p * t   (hop-2 message value)
__device__ float g_acc1[NMAX];  // sum of q[src] per dst
__device__ float g_acc2[NMAX];  // sum of r[src] per dst
__device__ int   g_mode;        // 1 = indices are int64, 0 = int32

// ---------------------------------------------------------------------------
// K1 (fused, block-specialized):
//   block 0, warp 0 additionally: detect index dtype
//   blocks [0, edgeBlocks)   : deg[dst] += 1, one edge per thread (deg from 0)
//   blocks [edgeBlocks, ...) : y[node] = x[node] . W   (warp handles NPW nodes)
__global__ void k_deg_dot(const float* __restrict__ x, const float* __restrict__ W,
                          const long long* __restrict__ edge,
                          int e_cnt, int n, int edgeBlocks) {
    if (blockIdx.x == 0 && threadIdx.x < 32) {
        long long v = edge[threadIdx.x];
        unsigned ok = __ballot_sync(0xffffffffu, v >= 0 && v < (long long)n);
        if (threadIdx.x == 0) g_mode = (ok == 0xffffffffu) ? 1 : 0;
    }
    if (blockIdx.x < edgeBlocks) {
        int e = blockIdx.x * blockDim.x + threadIdx.x;
        if (e < e_cnt) {
            // per-block dtype detect (cheap, deterministic, no cross-block race)
            __shared__ int s_mode;
            if (threadIdx.x < 32) {
                long long v = edge[threadIdx.x];
                unsigned ok = __ballot_sync(0xffffffffu, v >= 0 && v < (long long)n);
                if (threadIdx.x == 0) s_mode = (ok == 0xffffffffu) ? 1 : 0;
            }
            __syncthreads();
            int dst = s_mode ? (int)edge[e_cnt + e] : ((const int*)edge)[e_cnt + e];
            if ((unsigned)dst < (unsigned)n)
                atomicAdd(&g_deg[dst], 1.0f);
        }
    } else {
        int bid = blockIdx.x - edgeBlocks;
        int warp = (bid * blockDim.x + threadIdx.x) >> 5;
        int lane = threadIdx.x & 31;
        int base = warp * NPW;
        if (base >= n) return;

        float4 w = __ldg(&((const float4*)W)[lane]);

        float4 a[NPW];
        #pragma unroll
        for (int k = 0; k < NPW; k++) {
            int node = base + k;
            if (node < n)
                a[k] = ((const float4*)(x + (size_t)node * DD))[lane];
            else
                a[k] = make_float4(0.f, 0.f, 0.f, 0.f);
        }

        float s[NPW];
        #pragma unroll
        for (int k = 0; k < NPW; k++)
            s[k] = a[k].x * w.x + a[k].y * w.y + a[k].z * w.z + a[k].w * w.w;

        #pragma unroll
        for (int off = 16; off > 0; off >>= 1) {
            #pragma unroll
            for (int k = 0; k < NPW; k++)
                s[k] += __shfl_down_sync(0xffffffffu, s[k], off);
        }

        if (lane == 0) {
            #pragma unroll
            for (int k = 0; k < NPW; k++) {
                int node = base + k;
                if (node < n) g_y[node] = s[k];
            }
        }
    }
}

// ---------------------------------------------------------------------------
// K2: p = rsqrt(deg + 1)  (self-loop folded in), q = p*y
__global__ void k_pq(int n) {
    cudaGridDependencySynchronize();   // PDL: wait for k_deg_dot completion
    int i = blockIdx.x * blockDim.x + threadIdx.x;
    if (i < n) {
        float p = rsqrtf(g_deg[i] + 1.0f);
        g_p[i] = p;
        g_q[i] = p * g_y[i];
    }
}

// ---------------------------------------------------------------------------
// Edge sweep: acc[dst] += val[src].  ONE edge per thread (measured optimum).
__device__ __forceinline__ void edge_sweep(const long long* __restrict__ edge,
                                           int e_cnt, int n,
                                           const float* __restrict__ val,
                                           float* __restrict__ acc) {
    int e = blockIdx.x * blockDim.x + threadIdx.x;
    if (e < e_cnt) {
        int src, dst;
        if (g_mode) {
            src = (int)edge[e];
            dst = (int)edge[e_cnt + e];
        } else {
            const int* e32 = (const int*)edge;
            src = e32[e];
            dst = e32[e_cnt + e];
        }
        if ((unsigned)src < (unsigned)n && (unsigned)dst < (unsigned)n)
            atomicAdd(&acc[dst], val[src]);
    }
}

__global__ void k_hop1(const long long* __restrict__ edge, int e_cnt, int n) {
    cudaGridDependencySynchronize();   // PDL: wait for k_pq
    edge_sweep(edge, e_cnt, n, g_q, g_acc1);
}

__global__ void k_hop2(const long long* __restrict__ edge, int e_cnt, int n) {
    cudaGridDependencySynchronize();   // PDL: wait for k_mid
    edge_sweep(edge, e_cnt, n, g_r, g_acc2);
}

// ---------------------------------------------------------------------------
// K4: r = p*p*(q + acc1)
__global__ void k_mid(int n) {
    cudaGridDependencySynchronize();   // PDL: wait for k_hop1
    int i = blockIdx.x * blockDim.x + threadIdx.x;
    if (i < n) {
        float p = g_p[i];
        g_r[i] = p * p * (g_q[i] + g_acc1[i]);
    }
}

// K6: out[i] = p*(r + acc2) + b ; reset scratch to zero for the next call
__global__ void k_final(float* __restrict__ out, const float* __restrict__ b, int n) {
    cudaGridDependencySynchronize();   // PDL: wait for k_hop2
    int i = blockIdx.x * blockDim.x + threadIdx.x;
    if (i < n) {
        out[i] = g_p[i] * (g_r[i] + g_acc2[i]) + b[0];
        g_deg[i]  = 0.0f;
        g_acc1[i] = 0.0f;
        g_acc2[i] = 0.0f;
    }
}

// ---------------------------------------------------------------------------
template <typename... Args>
static inline void launch_pdl(void (*kern)(Args...), int grid, int block,
                              Args... args) {
    cudaLaunchConfig_t cfg = {};
    cfg.gridDim  = dim3(grid);
    cfg.blockDim = dim3(block);
    cudaLaunchAttribute attr[1];
    attr[0].id = cudaLaunchAttributeProgrammaticStreamSerialization;
    attr[0].val.programmaticStreamSerializationAllowed = 1;
    cfg.attrs = attr;
    cfg.numAttrs = 1;
    cudaLaunchKernelEx(&cfg, kern, args...);
}

extern "C" void kernel_launch(void* const* d_in, const int* in_sizes, int n_in,
                              void* d_out, int out_size) {
    const float*     x    = (const float*)d_in[0];       // [N, 128]
    const long long* edge = (const long long*)d_in[1];   // [2, E] indices
    const float*     W    = (const float*)d_in[2];       // [1, 128]
    const float*     b    = (const float*)d_in[3];       // [1]
    float*           out  = (float*)d_out;               // [N]

    int n = in_sizes[0] / DD;
    if (n > NMAX) n = NMAX;
    const int e_cnt = in_sizes[1] / 2;

    const int nBlkN = (n + TPB - 1) / TPB;
    const int nBlkE = (e_cnt + TPB - 1) / TPB;            // one edge / thread
    const int nWarps = (n + NPW - 1) / NPW;
    const int nBlkW = (nWarps * 32 + TPB - 1) / TPB;

    k_deg_dot<<<nBlkE + nBlkW, TPB>>>(x, W, edge, e_cnt, n, nBlkE);
    launch_pdl(k_pq, nBlkN, TPB, n);
    launch_pdl(k_hop1, nBlkE, TPB, edge, e_cnt, n);
    launch_pdl(k_mid, nBlkN, TPB, n);
    launch_pdl(k_hop2, nBlkE, TPB, edge, e_cnt, n);
    launch_pdl(k_final, nBlkN, TPB, out, b, n);
}

// round 16
// speedup vs baseline: 1.3655x; 1.0327x over previous
#include <cuda_runtime.h>
#include <stdint.h>

#define NMAX 50000
#define DD 128
#define NPW 8      // nodes per warp in proj-dot
#define TPB 256

// Scratch — zero-initialized at module load; every kernel_launch call leaves
// deg/acc1/acc2 zeroed again (k_final resets), so no init kernel is needed.
__device__ float g_deg[NMAX];
__device__ float g_y[NMAX];     // x . W
__device__ float g_p[NMAX];
__device__ float g_q[NMAX];     // p * y   (hop-1 message value)
__device__ float g_r[NMAX];     // p * t   (hop-2 message value)
__device__ float g_acc1[NMAX];  // sum of q[src] per dst
__device__ float g_acc2[NMAX];  // sum of r[src] per dst
__device__ int   g_mode;        // 1 = indices are int64, 0 = int32

// ---------------------------------------------------------------------------
// K1 (fused, block-specialized):
//   block 0, warp 0 additionally: detect index dtype -> g_mode
//   blocks [0, edgeBlocks)   : deg[dst] += 1, one edge per thread (deg from 0)
//   blocks [edgeBlocks, ...) : y[node] = x[node] . W   (warp handles NPW nodes)
__global__ void k_deg_dot(const float* __restrict__ x, const float* __restrict__ W,
                          const long long* __restrict__ edge,
                          int e_cnt, int n, int edgeBlocks) {
    if (blockIdx.x == 0 && threadIdx.x < 32) {
        long long v = edge[threadIdx.x];
        unsigned ok = __ballot_sync(0xffffffffu, v >= 0 && v < (long long)n);
        if (threadIdx.x == 0) g_mode = (ok == 0xffffffffu) ? 1 : 0;
    }
    if (blockIdx.x < edgeBlocks) {
        int e = blockIdx.x * blockDim.x + threadIdx.x;
        if (e < e_cnt) {
            // per-block dtype detect (cheap, deterministic, no cross-block race)
            __shared__ int s_mode;
            if (threadIdx.x < 32) {
                long long v = edge[threadIdx.x];
                unsigned ok = __ballot_sync(0xffffffffu, v >= 0 && v < (long long)n);
                if (threadIdx.x == 0) s_mode = (ok == 0xffffffffu) ? 1 : 0;
            }
            __syncthreads();
            int dst = s_mode ? (int)edge[e_cnt + e] : ((const int*)edge)[e_cnt + e];
            if ((unsigned)dst < (unsigned)n)
                atomicAdd(&g_deg[dst], 1.0f);
        }
    } else {
        int bid = blockIdx.x - edgeBlocks;
        int warp = (bid * blockDim.x + threadIdx.x) >> 5;
        int lane = threadIdx.x & 31;
        int base = warp * NPW;
        if (base >= n) return;

        float4 w = __ldg(&((const float4*)W)[lane]);

        float4 a[NPW];
        #pragma unroll
        for (int k = 0; k < NPW; k++) {
            int node = base + k;
            if (node < n)
                a[k] = ((const float4*)(x + (size_t)node * DD))[lane];
            else
                a[k] = make_float4(0.f, 0.f, 0.f, 0.f);
        }

        float s[NPW];
        #pragma unroll
        for (int k = 0; k < NPW; k++)
            s[k] = a[k].x * w.x + a[k].y * w.y + a[k].z * w.z + a[k].w * w.w;

        #pragma unroll
        for (int off = 16; off > 0; off >>= 1) {
            #pragma unroll
            for (int k = 0; k < NPW; k++)
                s[k] += __shfl_down_sync(0xffffffffu, s[k], off);
        }

        if (lane == 0) {
            #pragma unroll
            for (int k = 0; k < NPW; k++) {
                int node = base + k;
                if (node < n) g_y[node] = s[k];
            }
        }
    }
}

// ---------------------------------------------------------------------------
// K2: p = rsqrt(deg + 1), q = p*y.  Both inputs are from the immediate
// predecessor, so nothing is prefetchable here.
__global__ void k_pq(int n) {
    cudaGridDependencySynchronize();   // PDL: wait for k_deg_dot
    int i = blockIdx.x * blockDim.x + threadIdx.x;
    if (i < n) {
        float p = rsqrtf(g_deg[i] + 1.0f);
        g_p[i] = p;
        g_q[i] = p * g_y[i];
    }
}

// ---------------------------------------------------------------------------
// Hop sweep with PDL prelude: indices (harness input) and g_mode (written
// two kernels back, transitively visible) load BEFORE the dependency sync;
// only the value gather + atomic depend on the immediate predecessor.
__device__ __forceinline__ void edge_sweep_pdl(const long long* __restrict__ edge,
                                               int e_cnt, int n,
                                               const float* __restrict__ val,
                                               float* __restrict__ acc) {
    int e = blockIdx.x * blockDim.x + threadIdx.x;
    int src = 0, dst = -1;
    if (e < e_cnt) {
        if (g_mode) {
            src = (int)edge[e];
            dst = (int)edge[e_cnt + e];
        } else {
            const int* e32 = (const int*)edge;
            src = e32[e];
            dst = e32[e_cnt + e];
        }
    }
    cudaGridDependencySynchronize();   // PDL: predecessor writes now visible
    if ((unsigned)src < (unsigned)n && (unsigned)dst < (unsigned)n)
        atomicAdd(&acc[dst], val[src]);
}

__global__ void k_hop1(const long long* __restrict__ edge, int e_cnt, int n) {
    edge_sweep_pdl(edge, e_cnt, n, g_q, g_acc1);
}

__global__ void k_hop2(const long long* __restrict__ edge, int e_cnt, int n) {
    edge_sweep_pdl(edge, e_cnt, n, g_r, g_acc2);
}

// ---------------------------------------------------------------------------
// K4: r = p*p*(q + acc1).  p,q are from k_pq (two back) -> prefetch pre-sync;
// acc1 (hop1 atomics) read post-sync.
__global__ void k_mid(int n) {
    int i = blockIdx.x * blockDim.x + threadIdx.x;
    float p = 0.f, q = 0.f;
    if (i < n) {
        p = g_p[i];
        q = g_q[i];
    }
    cudaGridDependencySynchronize();   // PDL: wait for k_hop1 atomics
    if (i < n)
        g_r[i] = p * p * (q + g_acc1[i]);
}

// K6: out = p*(r + acc2) + b.  p (3 back), r (2 back), bias (input) prefetch;
// acc2 post-sync.  Also re-zero scratch for the next call.
__global__ void k_final(float* __restrict__ out, const float* __restrict__ b, int n) {
    int i = blockIdx.x * blockDim.x + threadIdx.x;
    float p = 0.f, r = 0.f;
    float bias = __ldg(&b[0]);
    if (i < n) {
        p = g_p[i];
        r = g_r[i];
    }
    cudaGridDependencySynchronize();   // PDL: wait for k_hop2 atomics
    if (i < n) {
        out[i] = p * (r + g_acc2[i]) + bias;
        g_deg[i]  = 0.0f;
        g_acc1[i] = 0.0f;
        g_acc2[i] = 0.0f;
    }
}

// ---------------------------------------------------------------------------
template <typename... Args>
static inline void launch_pdl(void (*kern)(Args...), int grid, int block,
                              Args... args) {
    cudaLaunchConfig_t cfg = {};
    cfg.gridDim  = dim3(grid);
    cfg.blockDim = dim3(block);
    cudaLaunchAttribute attr[1];
    attr[0].id = cudaLaunchAttributeProgrammaticStreamSerialization;
    attr[0].val.programmaticStreamSerializationAllowed = 1;
    cfg.attrs = attr;
    cfg.numAttrs = 1;
    cudaLaunchKernelEx(&cfg, kern, args...);
}

extern "C" void kernel_launch(void* const* d_in, const int* in_sizes, int n_in,
                              void* d_out, int out_size) {
    const float*     x    = (const float*)d_in[0];       // [N, 128]
    const long long* edge = (const long long*)d_in[1];   // [2, E] indices
    const float*     W    = (const float*)d_in[2];       // [1, 128]
    const float*     b    = (const float*)d_in[3];       // [1]
    float*           out  = (float*)d_out;               // [N]

    int n = in_sizes[0] / DD;
    if (n > NMAX) n = NMAX;
    const int e_cnt = in_sizes[1] / 2;

    const int nBlkN = (n + TPB - 1) / TPB;
    const int nBlkE = (e_cnt + TPB - 1) / TPB;            // one edge / thread
    const int nWarps = (n + NPW - 1) / NPW;
    const int nBlkW = (nWarps * 32 + TPB - 1) / TPB;

    k_deg_dot<<<nBlkE + nBlkW, TPB>>>(x, W, edge, e_cnt, n, nBlkE);
    launch_pdl(k_pq, nBlkN, TPB, n);
    launch_pdl(k_hop1, nBlkE, TPB, edge, e_cnt, n);
    launch_pdl(k_mid, nBlkN, TPB, n);
    launch_pdl(k_hop2, nBlkE, TPB, edge, e_cnt, n);
    launch_pdl(k_final, nBlkN, TPB, out, b, n);
}